// round 11
// baseline (speedup 1.0000x reference)
#include <cuda_runtime.h>
#include <cuda_bf16.h>
#include <math.h>
#include <stdint.h>

#define NB 256
#define TT 64
#define HH 1024
#define GG 4096
#define LL 16
#define KP 3072   // 3-term split folded into K

__device__ __forceinline__ uint32_t smem_u32(const void* p) {
    uint32_t a;
    asm("{ .reg .u64 t; cvta.to.shared.u64 t, %1; cvt.u32.u64 %0, t; }" : "=r"(a) : "l"(p));
    return a;
}
#define CP16(dst, src) asm volatile("cp.async.cg.shared.global [%0], [%1], 16;" :: "r"(dst), "l"(src) : "memory")
#define CP_COMMIT() asm volatile("cp.async.commit_group;" ::: "memory")
#define CP_WAIT1() asm volatile("cp.async.wait_group 1;" ::: "memory")
#define LDSM4(r0, r1, r2, r3, addr) \
    asm volatile("ldmatrix.sync.aligned.m8n8.x4.shared.b16 {%0,%1,%2,%3}, [%4];" \
        : "=r"(r0), "=r"(r1), "=r"(r2), "=r"(r3) : "r"(addr))
#define MMA16816(d, a, b) \
    asm volatile("mma.sync.aligned.m16n8k16.row.col.f32.bf16.bf16.f32 " \
        "{%0,%1,%2,%3}, {%4,%5,%6,%7}, {%8,%9}, {%0,%1,%2,%3};" \
        : "+f"((d)[0]), "+f"((d)[1]), "+f"((d)[2]), "+f"((d)[3]) \
        : "r"((a)[0]), "r"((a)[1]), "r"((a)[2]), "r"((a)[3]), "r"((b)[0]), "r"((b)[1]))

// ------------------------------------------------ scratch
__device__ float g_XW[(size_t)NB * TT * GG];      // permuted cols, fp32
__device__ float g_P[(size_t)NB * LL * GG];       // permuted cols, fp32
__device__ float g_AT[(size_t)NB * LL * HH];      // fp32 for scores
__device__ float g_pre[(size_t)NB * GG];          // h@Wh pre-activations (permuted)
__device__ float g_w[NB * LL];
__device__ float g_h[NB * HH];
__device__ float g_c[NB * HH];
__device__ float g_bperm[GG];
__device__ __nv_bfloat16 g_xs[(size_t)NB * TT * KP];     // [xhi|xlo|xhi]
__device__ __nv_bfloat16 g_ATs[(size_t)NB * LL * KP];    // [hi|lo|hi]
__device__ __nv_bfloat16 g_Wxs[(size_t)GG * KP];         // [hi|hi|lo] (B side)
__device__ __nv_bfloat16 g_Whs[(size_t)GG * KP];
__device__ __nv_bfloat16 g_Was[(size_t)GG * KP];
__device__ __nv_bfloat16 g_hsA[(size_t)NB * KP];         // h ping [hi|lo|hi]
__device__ __nv_bfloat16 g_hsB[(size_t)NB * KP];         // h pong

// ------------------------------------------------ prep kernels
__global__ void x_split_kernel(const float* __restrict__ x) {
    size_t gid = (size_t)blockIdx.x * 256 + threadIdx.x;  // float4 id
    size_t r = gid >> 8;
    int kq = (int)(gid & 255);
    float4 v = ((const float4*)x)[gid];
    __nv_bfloat162 h0 = __floats2bfloat162_rn(v.x, v.y);
    __nv_bfloat162 h1 = __floats2bfloat162_rn(v.z, v.w);
    float2 f0 = __bfloat1622float2(h0), f1 = __bfloat1622float2(h1);
    __nv_bfloat162 l0 = __floats2bfloat162_rn(v.x - f0.x, v.y - f0.y);
    __nv_bfloat162 l1 = __floats2bfloat162_rn(v.z - f1.x, v.w - f1.y);
    __nv_bfloat162* base = (__nv_bfloat162*)(g_xs + r * KP);
    base[kq * 2] = h0;         base[kq * 2 + 1] = h1;
    base[512 + kq * 2] = l0;   base[512 + kq * 2 + 1] = l1;
    base[1024 + kq * 2] = h0;  base[1024 + kq * 2 + 1] = h1;
}

__global__ void at_prep_kernel(const float* __restrict__ A) {
    int idx = blockIdx.x * 256 + threadIdx.x;  // n*1024 + h
    int n = idx >> 10, h = idx & 1023;
    const float4* a4 = (const float4*)(A + (size_t)idx * 16);
    float s = 0.f;
#pragma unroll
    for (int q = 0; q < 4; q++) {
        float4 v = a4[q];
        float vv[4] = {v.x, v.y, v.z, v.w};
#pragma unroll
        for (int e = 0; e < 4; e++) {
            int l = q * 4 + e;
            float val = vv[e];
            g_AT[((size_t)n * LL + l) * HH + h] = val;
            __nv_bfloat16 hi = __float2bfloat16(val);
            __nv_bfloat16 lo = __float2bfloat16(val - __bfloat162float(hi));
            size_t o = ((size_t)n * LL + l) * KP + h;
            g_ATs[o] = hi; g_ATs[o + 1024] = lo; g_ATs[o + 2048] = hi;
            s += val;
        }
    }
    float h0 = s * (1.0f / 16.0f);
    g_h[idx] = h0;
    g_c[idx] = h0;
    __nv_bfloat16 hh = __float2bfloat16(h0);
    __nv_bfloat16 hl = __float2bfloat16(h0 - __bfloat162float(hh));
    size_t o = (size_t)n * KP + h;
    g_hsA[o] = hh; g_hsA[o + 1024] = hl; g_hsA[o + 2048] = hh;
}

// transpose + split + permute: col c = g*1024+u -> rp = ((u>>3)<<5)|(g<<3)|(u&7)
__global__ void wsplit_kernel(const float* __restrict__ W, __nv_bfloat16* __restrict__ Ws) {
    __shared__ float tile[32][33];
    int c0 = blockIdx.x * 32, k0 = blockIdx.y * 32;
    int tx = threadIdx.x;
    for (int i = threadIdx.y; i < 32; i += 8)
        tile[i][tx] = W[(size_t)(k0 + i) * GG + c0 + tx];
    __syncthreads();
    for (int i = threadIdx.y; i < 32; i += 8) {
        int c = c0 + i;
        int u = c & 1023, g = c >> 10;
        int rp = ((u >> 3) << 5) | (g << 3) | (u & 7);
        float v = tile[tx][i];
        __nv_bfloat16 hi = __float2bfloat16(v);
        __nv_bfloat16 lo = __float2bfloat16(v - __bfloat162float(hi));
        size_t o = (size_t)rp * KP + k0 + tx;
        Ws[o] = hi; Ws[o + 1024] = hi; Ws[o + 2048] = lo;
    }
}

__global__ void bias_perm_kernel(const float* __restrict__ b) {
    int idx = blockIdx.x * 256 + threadIdx.x;   // permuted col
    int g = (idx >> 3) & 3;
    int u = (idx & 7) | ((idx >> 5) << 3);
    g_bperm[idx] = b[g * 1024 + u];
}

// ------------------------------------------------ phase-1 mma.sync bf16 GEMM
template <int BM, int BN, int WARPS_M, int WARPS_N, int EPI>
__global__ void __launch_bounds__(WARPS_M * WARPS_N * 32)
gemm_mma(const __nv_bfloat16* __restrict__ Ag, const __nv_bfloat16* __restrict__ Bg,
         float* __restrict__ Cout, const float* __restrict__ addv)
{
    constexpr int NTH = WARPS_M * WARPS_N * 32;
    constexpr int WM = BM / WARPS_M, WN = BN / WARPS_N;
    constexpr int MT = WM / 16, NT2 = WN / 8;
    constexpr int KC = KP / 64;
    constexpr int ABUF = BM * 128, BBUF = BN * 128;

    extern __shared__ char smem[];
    const uint32_t sA = smem_u32(smem);
    const uint32_t sB = sA + 2 * ABUF;
    const int tid = threadIdx.x, lane = tid & 31, warp = tid >> 5;
    const int wm0 = (warp / WARPS_N) * WM, wn0 = (warp % WARPS_N) * WN;
    const int m0 = blockIdx.y * BM, n0 = blockIdx.x * BN;
    const __nv_bfloat16* Abase = Ag + (size_t)m0 * KP;
    const __nv_bfloat16* Bbase = Bg + (size_t)n0 * KP;

    float acc[MT][NT2][4];
#pragma unroll
    for (int i = 0; i < MT; i++)
#pragma unroll
        for (int j = 0; j < NT2; j++)
#pragma unroll
            for (int e = 0; e < 4; e++) acc[i][j][e] = 0.f;

#define ISSUE1(kc, buf) do { \
    const __nv_bfloat16* As_ = Abase + (kc) * 64; \
    _Pragma("unroll") \
    for (int i = 0; i < BM * 8 / NTH; i++) { \
        int idx = tid + i * NTH, r = idx >> 3, q = idx & 7; \
        CP16(sA + (buf) * ABUF + r * 128 + (((q ^ (r & 7)) << 4)), As_ + (size_t)r * KP + q * 8); \
    } \
    const __nv_bfloat16* Bs_ = Bbase + (kc) * 64; \
    _Pragma("unroll") \
    for (int i = 0; i < BN * 8 / NTH; i++) { \
        int idx = tid + i * NTH, r = idx >> 3, q = idx & 7; \
        CP16(sB + (buf) * BBUF + r * 128 + (((q ^ (r & 7)) << 4)), Bs_ + (size_t)r * KP + q * 8); \
    } \
} while (0)

    ISSUE1(0, 0); CP_COMMIT();
    ISSUE1(1, 1); CP_COMMIT();

    for (int kc = 0; kc < KC; kc++) {
        CP_WAIT1();
        __syncthreads();
        const int buf = kc & 1;
        const uint32_t a0b = sA + buf * ABUF, b0b = sB + buf * BBUF;
#pragma unroll
        for (int ks = 0; ks < 4; ks++) {
            uint32_t af[MT][4], bf[NT2][2];
#pragma unroll
            for (int mt = 0; mt < MT; mt++) {
                int r = wm0 + mt * 16 + (lane & 15);
                int q = ks * 2 + (lane >> 4);
                LDSM4(af[mt][0], af[mt][1], af[mt][2], af[mt][3],
                      a0b + r * 128 + (((q ^ (r & 7)) << 4)));
            }
#pragma unroll
            for (int p = 0; p < NT2 / 2; p++) {
                int n = wn0 + p * 16 + (lane & 7) + ((lane >> 4) << 3);
                int q = ks * 2 + ((lane >> 3) & 1);
                LDSM4(bf[2 * p][0], bf[2 * p][1], bf[2 * p + 1][0], bf[2 * p + 1][1],
                      b0b + n * 128 + (((q ^ (n & 7)) << 4)));
            }
#pragma unroll
            for (int mt = 0; mt < MT; mt++)
#pragma unroll
                for (int nt = 0; nt < NT2; nt++)
                    MMA16816(acc[mt][nt], af[mt], bf[nt]);
        }
        __syncthreads();
        if (kc + 2 < KC) ISSUE1(kc + 2, buf);
        CP_COMMIT();
    }
#undef ISSUE1

    const int l4 = lane >> 2, q2 = (lane & 3) * 2;
#pragma unroll
    for (int mt = 0; mt < MT; mt++) {
        int r0 = m0 + wm0 + mt * 16 + l4;
#pragma unroll
        for (int nt = 0; nt < NT2; nt++) {
            int col = n0 + wn0 + nt * 8 + q2;
            float bx = 0.f, by = 0.f;
            if (EPI == 1) { bx = addv[col]; by = addv[col + 1]; }
            *(float2*)(Cout + (size_t)r0 * GG + col) =
                make_float2(acc[mt][nt][0] + bx, acc[mt][nt][1] + by);
            *(float2*)(Cout + (size_t)(r0 + 8) * GG + col) =
                make_float2(acc[mt][nt][2] + bx, acc[mt][nt][3] + by);
        }
    }
}

// ------------------------------------------------ step kernel 1: gemm + scores
// CTAs 0..127: 64x128 tile of pre = h' @ Whs^T   (BM=64,BN=128,WM=2,WN=4)
// CTAs 128..383: scores+softmax for sample n = bid-128
__global__ void __launch_bounds__(256)
megastep1(const __nv_bfloat16* __restrict__ hcur)
{
    const int bid = blockIdx.x;
    const int tid = threadIdx.x, lane = tid & 31, warp = tid >> 5;

    if (bid >= 128) {
        // ---------------- scores path ----------------
        __shared__ float sw[16];
        const int n = bid - 128;
        const float* hp = g_h + (size_t)n * HH;
        const float* a0 = g_AT + ((size_t)n * LL + warp * 2) * HH;
        const float* a1 = a0 + HH;
        float acc0 = 0.f, acc1 = 0.f;
        for (int k = lane; k < HH; k += 32) {
            float hv = hp[k];
            acc0 += hv * a0[k];
            acc1 += hv * a1[k];
        }
#pragma unroll
        for (int o = 16; o > 0; o >>= 1) {
            acc0 += __shfl_xor_sync(0xffffffffu, acc0, o);
            acc1 += __shfl_xor_sync(0xffffffffu, acc1, o);
        }
        if (lane == 0) { sw[warp * 2] = acc0 * 0.03125f; sw[warp * 2 + 1] = acc1 * 0.03125f; }
        __syncthreads();
        if (warp == 0) {
            float s = (lane < 16) ? sw[lane] : -1e30f;
            float m = s;
#pragma unroll
            for (int o = 16; o > 0; o >>= 1) m = fmaxf(m, __shfl_xor_sync(0xffffffffu, m, o));
            float e = (lane < 16) ? expf(s - m) : 0.f;
            float tot = e;
#pragma unroll
            for (int o = 16; o > 0; o >>= 1) tot += __shfl_xor_sync(0xffffffffu, tot, o);
            if (lane < 16) g_w[n * LL + lane] = e / tot;
        }
        return;
    }

    // ---------------- gemm path (BM=64, BN=128) ----------------
    constexpr int ABUF = 64 * 128, BBUF = 128 * 128;
    extern __shared__ char smem[];
    const uint32_t sA = smem_u32(smem);
    const uint32_t sB = sA + 2 * ABUF;
    const int wm0 = (warp >> 2) * 32, wn0 = (warp & 3) * 32;   // WARPS_M=2, WARPS_N=4
    const int m0 = (bid >> 5) * 64, n0 = (bid & 31) * 128;
    const __nv_bfloat16* Abase = hcur + (size_t)m0 * KP;
    const __nv_bfloat16* Bbase = g_Whs + (size_t)n0 * KP;

    float acc[2][4][4];
#pragma unroll
    for (int i = 0; i < 2; i++)
#pragma unroll
        for (int j = 0; j < 4; j++)
#pragma unroll
            for (int e = 0; e < 4; e++) acc[i][j][e] = 0.f;

#define ISSUE2(kc, buf) do { \
    const __nv_bfloat16* As_ = Abase + (kc) * 64; \
    _Pragma("unroll") \
    for (int i = 0; i < 2; i++) { \
        int idx = tid + i * 256, r = idx >> 3, q = idx & 7; \
        CP16(sA + (buf) * ABUF + r * 128 + (((q ^ (r & 7)) << 4)), As_ + (size_t)r * KP + q * 8); \
    } \
    const __nv_bfloat16* Bs_ = Bbase + (kc) * 64; \
    _Pragma("unroll") \
    for (int i = 0; i < 4; i++) { \
        int idx = tid + i * 256, r = idx >> 3, q = idx & 7; \
        CP16(sB + (buf) * BBUF + r * 128 + (((q ^ (r & 7)) << 4)), Bs_ + (size_t)r * KP + q * 8); \
    } \
} while (0)

    ISSUE2(0, 0); CP_COMMIT();
    ISSUE2(1, 1); CP_COMMIT();

    for (int kc = 0; kc < KP / 64; kc++) {
        CP_WAIT1();
        __syncthreads();
        const int buf = kc & 1;
        const uint32_t a0b = sA + buf * ABUF, b0b = sB + buf * BBUF;
#pragma unroll
        for (int ks = 0; ks < 4; ks++) {
            uint32_t af[2][4], bf[4][2];
#pragma unroll
            for (int mt = 0; mt < 2; mt++) {
                int r = wm0 + mt * 16 + (lane & 15);
                int q = ks * 2 + (lane >> 4);
                LDSM4(af[mt][0], af[mt][1], af[mt][2], af[mt][3],
                      a0b + r * 128 + (((q ^ (r & 7)) << 4)));
            }
#pragma unroll
            for (int p = 0; p < 2; p++) {
                int nn = wn0 + p * 16 + (lane & 7) + ((lane >> 4) << 3);
                int q = ks * 2 + ((lane >> 3) & 1);
                LDSM4(bf[2 * p][0], bf[2 * p][1], bf[2 * p + 1][0], bf[2 * p + 1][1],
                      b0b + nn * 128 + (((q ^ (nn & 7)) << 4)));
            }
#pragma unroll
            for (int mt = 0; mt < 2; mt++)
#pragma unroll
                for (int nt = 0; nt < 4; nt++)
                    MMA16816(acc[mt][nt], af[mt], bf[nt]);
        }
        __syncthreads();
        if (kc + 2 < KP / 64) ISSUE2(kc + 2, buf);
        CP_COMMIT();
    }
#undef ISSUE2

    const int l4 = lane >> 2, q2 = (lane & 3) * 2;
#pragma unroll
    for (int mt = 0; mt < 2; mt++) {
        int r0 = m0 + wm0 + mt * 16 + l4;
#pragma unroll
        for (int nt = 0; nt < 4; nt++) {
            int col = n0 + wn0 + nt * 8 + q2;
            *(float2*)(g_pre + (size_t)r0 * GG + col) =
                make_float2(acc[mt][nt][0], acc[mt][nt][1]);
            *(float2*)(g_pre + (size_t)(r0 + 8) * GG + col) =
                make_float2(acc[mt][nt][2], acc[mt][nt][3]);
        }
    }
}

// ------------------------------------------------ step kernel 2: combine + gates
// One CTA per sample n. z = XW_t + sum_l w_l P_l staged in smem, then gates.
__global__ void __launch_bounds__(256)
megastep2(float* __restrict__ out, __nv_bfloat16* __restrict__ hnxt, int t)
{
    __shared__ float zs[GG];
    const int n = blockIdx.x;
    const int tid = threadIdx.x;
    float wl[16];
#pragma unroll
    for (int l = 0; l < 16; l++) wl[l] = g_w[n * LL + l];

    const float4* xw4 = (const float4*)(g_XW + ((size_t)n * TT + t) * GG);
    const float4* p4 = (const float4*)(g_P + (size_t)n * LL * GG);
#pragma unroll
    for (int it = 0; it < 4; it++) {
        int c = tid + it * 256;                  // float4 idx 0..1023
        float4 a = xw4[c];
#pragma unroll
        for (int l = 0; l < 16; l++) {
            float4 pv = p4[(size_t)l * (GG / 4) + c];
            float w = wl[l];
            a.x += w * pv.x; a.y += w * pv.y; a.z += w * pv.z; a.w += w * pv.w;
        }
        ((float4*)zs)[c] = a;
    }
    __syncthreads();

    const float* pre = g_pre + (size_t)n * GG;
#pragma unroll
    for (int it = 0; it < 4; it++) {
        int u = tid + it * 256;
        int base = ((u >> 3) << 5) | (u & 7);
        float ai = pre[base] + zs[base];
        float af = pre[base + 8] + zs[base + 8];
        float ao = pre[base + 16] + zs[base + 16];
        float ag = pre[base + 24] + zs[base + 24];
        float gi = 1.f / (1.f + expf(-ai));
        float gf = 1.f / (1.f + expf(-af));
        float go = 1.f / (1.f + expf(-ao));
        float gg = tanhf(ag);
        int idx = n * HH + u;
        float cn = gf * g_c[idx] + gi * gg;
        g_c[idx] = cn;
        float hn = go * tanhf(cn);
        g_h[idx] = hn;
        __nv_bfloat16 hh = __float2bfloat16(hn);
        __nv_bfloat16 hl = __float2bfloat16(hn - __bfloat162float(hh));
        size_t hb = (size_t)n * KP + u;
        hnxt[hb] = hh; hnxt[hb + 1024] = hl; hnxt[hb + 2048] = hh;
        out[((size_t)n * TT + t) * HH + u] = hn;
    }
}

// ------------------------------------------------ launch
extern "C" void kernel_launch(void* const* d_in, const int* in_sizes, int n_in,
                              void* d_out, int out_size) {
    const float* x = (const float*)d_in[0];
    const float* A = (const float*)d_in[1];
    const float* Wx = (const float*)d_in[2];
    const float* Wh = (const float*)d_in[3];
    const float* Wattn = (const float*)d_in[4];
    const float* b = (const float*)d_in[5];
    float* out = (float*)d_out;

    float *p_xw, *p_p, *p_bp;
    __nv_bfloat16 *p_xs, *p_ats, *p_wxs, *p_whs, *p_was, *p_hsA, *p_hsB;
    cudaGetSymbolAddress((void**)&p_xw, g_XW);
    cudaGetSymbolAddress((void**)&p_p, g_P);
    cudaGetSymbolAddress((void**)&p_bp, g_bperm);
    cudaGetSymbolAddress((void**)&p_xs, g_xs);
    cudaGetSymbolAddress((void**)&p_ats, g_ATs);
    cudaGetSymbolAddress((void**)&p_wxs, g_Wxs);
    cudaGetSymbolAddress((void**)&p_whs, g_Whs);
    cudaGetSymbolAddress((void**)&p_was, g_Was);
    cudaGetSymbolAddress((void**)&p_hsA, g_hsA);
    cudaGetSymbolAddress((void**)&p_hsB, g_hsB);

    constexpr int SM_P1 = 2 * (128 + 128) * 128;  // 65536
    constexpr int SM_ST = 2 * (64 + 128) * 128;   // 49152
    cudaFuncSetAttribute((const void*)gemm_mma<128, 128, 2, 4, 1>,
                         cudaFuncAttributeMaxDynamicSharedMemorySize, SM_P1);
    cudaFuncSetAttribute((const void*)gemm_mma<128, 128, 2, 4, 0>,
                         cudaFuncAttributeMaxDynamicSharedMemorySize, SM_P1);
    cudaFuncSetAttribute((const void*)megastep1,
                         cudaFuncAttributeMaxDynamicSharedMemorySize, SM_ST);

    // prep
    x_split_kernel<<<(NB * TT * HH / 4) / 256, 256>>>(x);
    at_prep_kernel<<<(NB * HH) / 256, 256>>>(A);
    {
        dim3 g(GG / 32, HH / 32), blk(32, 8);
        wsplit_kernel<<<g, blk>>>(Wx, p_wxs);
        wsplit_kernel<<<g, blk>>>(Wh, p_whs);
        wsplit_kernel<<<g, blk>>>(Wattn, p_was);
    }
    bias_perm_kernel<<<GG / 256, 256>>>(b);

    // phase 1: XW = x' @ Wx'^T + b ; P = AT' @ Wa'^T
    {
        dim3 g(GG / 128, (NB * TT) / 128);
        gemm_mma<128, 128, 2, 4, 1><<<g, 256, SM_P1>>>(p_xs, p_wxs, p_xw, p_bp);
    }
    {
        dim3 g(GG / 128, (NB * LL) / 128);
        gemm_mma<128, 128, 2, 4, 0><<<g, 256, SM_P1>>>(p_ats, p_was, p_p, nullptr);
    }

    // phase 2: 2 launches per step (gemm+scores heterogeneous, then combine+gates)
    for (int t = 0; t < TT; t++) {
        const __nv_bfloat16* hc = (t & 1) ? p_hsB : p_hsA;
        __nv_bfloat16* hn = (t & 1) ? p_hsA : p_hsB;
        megastep1<<<384, 256, SM_ST>>>(hc);
        megastep2<<<NB, 256>>>(out, hn, t);
    }
}

// round 13
// speedup vs baseline: 1.2548x; 1.2548x over previous
#include <cuda_runtime.h>
#include <cuda_bf16.h>
#include <math.h>
#include <stdint.h>

#define NB 256
#define TT 64
#define HH 1024
#define GG 4096
#define LL 16
#define KP 3072   // 3-term split folded into K

__device__ __forceinline__ uint32_t smem_u32(const void* p) {
    uint32_t a;
    asm("{ .reg .u64 t; cvta.to.shared.u64 t, %1; cvt.u32.u64 %0, t; }" : "=r"(a) : "l"(p));
    return a;
}
#define CP16(dst, src) asm volatile("cp.async.cg.shared.global [%0], [%1], 16;" :: "r"(dst), "l"(src) : "memory")
#define CP_COMMIT() asm volatile("cp.async.commit_group;" ::: "memory")
#define CP_WAIT1() asm volatile("cp.async.wait_group 1;" ::: "memory")
#define LDSM4(r0, r1, r2, r3, addr) \
    asm volatile("ldmatrix.sync.aligned.m8n8.x4.shared.b16 {%0,%1,%2,%3}, [%4];" \
        : "=r"(r0), "=r"(r1), "=r"(r2), "=r"(r3) : "r"(addr))
#define MMA16816(d, a, b) \
    asm volatile("mma.sync.aligned.m16n8k16.row.col.f32.bf16.bf16.f32 " \
        "{%0,%1,%2,%3}, {%4,%5,%6,%7}, {%8,%9}, {%0,%1,%2,%3};" \
        : "+f"((d)[0]), "+f"((d)[1]), "+f"((d)[2]), "+f"((d)[3]) \
        : "r"((a)[0]), "r"((a)[1]), "r"((a)[2]), "r"((a)[3]), "r"((b)[0]), "r"((b)[1]))

// ------------------------------------------------ scratch
__device__ float g_XW[(size_t)NB * TT * GG];      // permuted cols, fp32
__device__ float g_P[(size_t)NB * LL * GG];       // permuted cols, fp32
__device__ float g_AT[(size_t)NB * LL * HH];      // fp32 for scores
__device__ float g_attnZ[(size_t)NB * GG];        // permuted cols
__device__ float g_h[NB * HH];
__device__ float g_c[NB * HH];
__device__ float g_bperm[GG];
__device__ __nv_bfloat16 g_xs[(size_t)NB * TT * KP];     // [xhi|xlo|xhi]
__device__ __nv_bfloat16 g_ATs[(size_t)NB * LL * KP];    // [hi|lo|hi]
__device__ __nv_bfloat16 g_Wxs[(size_t)GG * KP];         // [hi|hi|lo] (B side)
__device__ __nv_bfloat16 g_Whs[(size_t)GG * KP];
__device__ __nv_bfloat16 g_Was[(size_t)GG * KP];
__device__ __nv_bfloat16 g_hsA[(size_t)NB * KP];         // h ping [hi|lo|hi]
__device__ __nv_bfloat16 g_hsB[(size_t)NB * KP];         // h pong

// ------------------------------------------------ prep kernels
__global__ void x_split_kernel(const float* __restrict__ x) {
    size_t gid = (size_t)blockIdx.x * 256 + threadIdx.x;  // float4 id
    size_t r = gid >> 8;
    int kq = (int)(gid & 255);
    float4 v = ((const float4*)x)[gid];
    __nv_bfloat162 h0 = __floats2bfloat162_rn(v.x, v.y);
    __nv_bfloat162 h1 = __floats2bfloat162_rn(v.z, v.w);
    float2 f0 = __bfloat1622float2(h0), f1 = __bfloat1622float2(h1);
    __nv_bfloat162 l0 = __floats2bfloat162_rn(v.x - f0.x, v.y - f0.y);
    __nv_bfloat162 l1 = __floats2bfloat162_rn(v.z - f1.x, v.w - f1.y);
    __nv_bfloat162* base = (__nv_bfloat162*)(g_xs + r * KP);
    base[kq * 2] = h0;         base[kq * 2 + 1] = h1;
    base[512 + kq * 2] = l0;   base[512 + kq * 2 + 1] = l1;
    base[1024 + kq * 2] = h0;  base[1024 + kq * 2 + 1] = h1;
}

__global__ void at_prep_kernel(const float* __restrict__ A) {
    int idx = blockIdx.x * 256 + threadIdx.x;  // n*1024 + h
    int n = idx >> 10, h = idx & 1023;
    const float4* a4 = (const float4*)(A + (size_t)idx * 16);
    float s = 0.f;
#pragma unroll
    for (int q = 0; q < 4; q++) {
        float4 v = a4[q];
        float vv[4] = {v.x, v.y, v.z, v.w};
#pragma unroll
        for (int e = 0; e < 4; e++) {
            int l = q * 4 + e;
            float val = vv[e];
            g_AT[((size_t)n * LL + l) * HH + h] = val;
            __nv_bfloat16 hi = __float2bfloat16(val);
            __nv_bfloat16 lo = __float2bfloat16(val - __bfloat162float(hi));
            size_t o = ((size_t)n * LL + l) * KP + h;
            g_ATs[o] = hi; g_ATs[o + 1024] = lo; g_ATs[o + 2048] = hi;
            s += val;
        }
    }
    float h0 = s * (1.0f / 16.0f);
    g_h[idx] = h0;
    g_c[idx] = h0;
    __nv_bfloat16 hh = __float2bfloat16(h0);
    __nv_bfloat16 hl = __float2bfloat16(h0 - __bfloat162float(hh));
    size_t o = (size_t)n * KP + h;
    g_hsA[o] = hh; g_hsA[o + 1024] = hl; g_hsA[o + 2048] = hh;
}

// transpose + split + permute: col c = g*1024+u -> rp = ((u>>3)<<5)|(g<<3)|(u&7)
__global__ void wsplit_kernel(const float* __restrict__ W, __nv_bfloat16* __restrict__ Ws) {
    __shared__ float tile[32][33];
    int c0 = blockIdx.x * 32, k0 = blockIdx.y * 32;
    int tx = threadIdx.x;
    for (int i = threadIdx.y; i < 32; i += 8)
        tile[i][tx] = W[(size_t)(k0 + i) * GG + c0 + tx];
    __syncthreads();
    for (int i = threadIdx.y; i < 32; i += 8) {
        int c = c0 + i;
        int u = c & 1023, g = c >> 10;
        int rp = ((u >> 3) << 5) | (g << 3) | (u & 7);
        float v = tile[tx][i];
        __nv_bfloat16 hi = __float2bfloat16(v);
        __nv_bfloat16 lo = __float2bfloat16(v - __bfloat162float(hi));
        size_t o = (size_t)rp * KP + k0 + tx;
        Ws[o] = hi; Ws[o + 1024] = hi; Ws[o + 2048] = lo;
    }
}

__global__ void bias_perm_kernel(const float* __restrict__ b) {
    int idx = blockIdx.x * 256 + threadIdx.x;   // permuted col
    int g = (idx >> 3) & 3;
    int u = (idx & 7) | ((idx >> 5) << 3);
    g_bperm[idx] = b[g * 1024 + u];
}

// ------------------------------------------------ mma.sync bf16 GEMM, K'=3072
// EPI: 0 plain, 1 +bias, 2 fused LSTM gates (BM=64, BN=64, 128 thr)
template <int BM, int BN, int WARPS_M, int WARPS_N, int EPI>
__global__ void __launch_bounds__(WARPS_M * WARPS_N * 32)
gemm_mma(const __nv_bfloat16* __restrict__ Ag, const __nv_bfloat16* __restrict__ Bg,
         float* __restrict__ Cout, const float* __restrict__ addv,
         __nv_bfloat16* __restrict__ hnext, float* __restrict__ out, int t)
{
    constexpr int NTH = WARPS_M * WARPS_N * 32;
    constexpr int WM = BM / WARPS_M, WN = BN / WARPS_N;
    constexpr int MT = WM / 16, NT2 = WN / 8;
    constexpr int KC = KP / 64;
    constexpr int ABUF = BM * 128, BBUF = BN * 128;

    extern __shared__ char smem[];
    const uint32_t sA = smem_u32(smem);
    const uint32_t sB = sA + 2 * ABUF;
    const int tid = threadIdx.x, lane = tid & 31, warp = tid >> 5;
    const int wm0 = (warp / WARPS_N) * WM, wn0 = (warp % WARPS_N) * WN;
    const int m0 = blockIdx.y * BM, n0 = blockIdx.x * BN;
    const __nv_bfloat16* Abase = Ag + (size_t)m0 * KP;
    const __nv_bfloat16* Bbase = Bg + (size_t)n0 * KP;

    float acc[MT][NT2][4];
#pragma unroll
    for (int i = 0; i < MT; i++)
#pragma unroll
        for (int j = 0; j < NT2; j++)
#pragma unroll
            for (int e = 0; e < 4; e++) acc[i][j][e] = 0.f;

#define ISSUE1(kc, buf) do { \
    const __nv_bfloat16* As_ = Abase + (kc) * 64; \
    _Pragma("unroll") \
    for (int i = 0; i < BM * 8 / NTH; i++) { \
        int idx = tid + i * NTH, r = idx >> 3, q = idx & 7; \
        CP16(sA + (buf) * ABUF + r * 128 + (((q ^ (r & 7)) << 4)), As_ + (size_t)r * KP + q * 8); \
    } \
    const __nv_bfloat16* Bs_ = Bbase + (kc) * 64; \
    _Pragma("unroll") \
    for (int i = 0; i < BN * 8 / NTH; i++) { \
        int idx = tid + i * NTH, r = idx >> 3, q = idx & 7; \
        CP16(sB + (buf) * BBUF + r * 128 + (((q ^ (r & 7)) << 4)), Bs_ + (size_t)r * KP + q * 8); \
    } \
} while (0)

    ISSUE1(0, 0); CP_COMMIT();
    ISSUE1(1, 1); CP_COMMIT();

    for (int kc = 0; kc < KC; kc++) {
        CP_WAIT1();
        __syncthreads();
        const int buf = kc & 1;
        const uint32_t a0b = sA + buf * ABUF, b0b = sB + buf * BBUF;
#pragma unroll
        for (int ks = 0; ks < 4; ks++) {
            uint32_t af[MT][4], bf[NT2][2];
#pragma unroll
            for (int mt = 0; mt < MT; mt++) {
                int r = wm0 + mt * 16 + (lane & 15);
                int q = ks * 2 + (lane >> 4);
                LDSM4(af[mt][0], af[mt][1], af[mt][2], af[mt][3],
                      a0b + r * 128 + (((q ^ (r & 7)) << 4)));
            }
#pragma unroll
            for (int p = 0; p < NT2 / 2; p++) {
                int n = wn0 + p * 16 + (lane & 7) + ((lane >> 4) << 3);
                int q = ks * 2 + ((lane >> 3) & 1);
                LDSM4(bf[2 * p][0], bf[2 * p][1], bf[2 * p + 1][0], bf[2 * p + 1][1],
                      b0b + n * 128 + (((q ^ (n & 7)) << 4)));
            }
#pragma unroll
            for (int mt = 0; mt < MT; mt++)
#pragma unroll
                for (int nt = 0; nt < NT2; nt++)
                    MMA16816(acc[mt][nt], af[mt], bf[nt]);
        }
        __syncthreads();
        if (kc + 2 < KC) ISSUE1(kc + 2, buf);
        CP_COMMIT();
    }
#undef ISSUE1

    const int l4 = lane >> 2, q2 = (lane & 3) * 2;
    if (EPI != 2) {
#pragma unroll
        for (int mt = 0; mt < MT; mt++) {
            int r0 = m0 + wm0 + mt * 16 + l4;
#pragma unroll
            for (int nt = 0; nt < NT2; nt++) {
                int col = n0 + wn0 + nt * 8 + q2;
                float bx = 0.f, by = 0.f;
                if (EPI == 1) { bx = addv[col]; by = addv[col + 1]; }
                *(float2*)(Cout + (size_t)r0 * GG + col) =
                    make_float2(acc[mt][nt][0] + bx, acc[mt][nt][1] + by);
                *(float2*)(Cout + (size_t)(r0 + 8) * GG + col) =
                    make_float2(acc[mt][nt][2] + bx, acc[mt][nt][3] + by);
            }
        }
    } else {
        const int U0 = (((n0 + wn0) >> 5) << 3) + q2;
        const int cb = n0 + wn0 + q2;
#pragma unroll
        for (int mt = 0; mt < MT; mt++) {
#pragma unroll
            for (int rs = 0; rs < 2; rs++) {
                int row = m0 + wm0 + mt * 16 + l4 + rs * 8;
                const float* zr = addv + (size_t)row * GG + cb;
#pragma unroll
                for (int us = 0; us < 2; us++) {
                    float ai = acc[mt][0][rs * 2 + us] + zr[us];
                    float afv = acc[mt][1][rs * 2 + us] + zr[8 + us];
                    float ao = acc[mt][2][rs * 2 + us] + zr[16 + us];
                    float ag = acc[mt][3][rs * 2 + us] + zr[24 + us];
                    int u = U0 + us;
                    float gi = 1.f / (1.f + expf(-ai));
                    float gf = 1.f / (1.f + expf(-afv));
                    float go = 1.f / (1.f + expf(-ao));
                    float gg = tanhf(ag);
                    size_t hx = (size_t)row * HH + u;
                    float cn = gf * g_c[hx] + gi * gg;
                    g_c[hx] = cn;
                    float hn = go * tanhf(cn);
                    g_h[hx] = hn;
                    __nv_bfloat16 hh = __float2bfloat16(hn);
                    __nv_bfloat16 hl = __float2bfloat16(hn - __bfloat162float(hh));
                    size_t hb = (size_t)row * KP + u;
                    hnext[hb] = hh; hnext[hb + 1024] = hl; hnext[hb + 2048] = hh;
                    out[((size_t)row * TT + t) * HH + u] = hn;
                }
            }
        }
    }
}

// ------------------------------------------------ fused scores+softmax+combine
// One CTA per sample n, 512 threads (16 warps).
__global__ __launch_bounds__(512) void sc_combine_kernel(int t) {
    __shared__ float sw[16];
    const int n = blockIdx.x;
    const int tid = threadIdx.x, warp = tid >> 5, lane = tid & 31;

    // scores: warp l computes dot(h[n,:], AT[n,l,:]) / 32
    {
        const float* hp = g_h + (size_t)n * HH;
        const float* ap = g_AT + ((size_t)n * LL + warp) * HH;
        float acc = 0.f;
        for (int k = lane; k < HH; k += 32) acc += hp[k] * ap[k];
#pragma unroll
        for (int o = 16; o > 0; o >>= 1) acc += __shfl_xor_sync(0xffffffffu, acc, o);
        if (lane == 0) sw[warp] = acc * 0.03125f;
    }
    __syncthreads();
    // softmax over 16 (warp 0)
    if (warp == 0) {
        float s = (lane < 16) ? sw[lane] : -1e30f;
        float m = s;
#pragma unroll
        for (int o = 16; o > 0; o >>= 1) m = fmaxf(m, __shfl_xor_sync(0xffffffffu, m, o));
        float e = (lane < 16) ? expf(s - m) : 0.f;
        float tot = e;
#pragma unroll
        for (int o = 16; o > 0; o >>= 1) tot += __shfl_xor_sync(0xffffffffu, tot, o);
        if (lane < 16) sw[lane] = e / tot;
    }
    __syncthreads();

    float wl[16];
#pragma unroll
    for (int l = 0; l < 16; l++) wl[l] = sw[l];

    const float4* xw4 = (const float4*)(g_XW + ((size_t)n * TT + t) * GG);
    const float4* p4 = (const float4*)(g_P + (size_t)n * LL * GG);
    float4* oz4 = (float4*)(g_attnZ + (size_t)n * GG);
#pragma unroll
    for (int it = 0; it < 2; it++) {
        int c = tid + it * 512;            // float4 idx 0..1023
        float4 a = xw4[c];
#pragma unroll
        for (int l = 0; l < 16; l++) {
            float4 pv = p4[(size_t)l * (GG / 4) + c];
            float w = wl[l];
            a.x += w * pv.x; a.y += w * pv.y; a.z += w * pv.z; a.w += w * pv.w;
        }
        oz4[c] = a;
    }
}

// ------------------------------------------------ launch
extern "C" void kernel_launch(void* const* d_in, const int* in_sizes, int n_in,
                              void* d_out, int out_size) {
    const float* x = (const float*)d_in[0];
    const float* A = (const float*)d_in[1];
    const float* Wx = (const float*)d_in[2];
    const float* Wh = (const float*)d_in[3];
    const float* Wattn = (const float*)d_in[4];
    const float* b = (const float*)d_in[5];
    float* out = (float*)d_out;

    float *p_xw, *p_p, *p_bp, *p_z;
    __nv_bfloat16 *p_xs, *p_ats, *p_wxs, *p_whs, *p_was, *p_hsA, *p_hsB;
    cudaGetSymbolAddress((void**)&p_xw, g_XW);
    cudaGetSymbolAddress((void**)&p_p, g_P);
    cudaGetSymbolAddress((void**)&p_bp, g_bperm);
    cudaGetSymbolAddress((void**)&p_z, g_attnZ);
    cudaGetSymbolAddress((void**)&p_xs, g_xs);
    cudaGetSymbolAddress((void**)&p_ats, g_ATs);
    cudaGetSymbolAddress((void**)&p_wxs, g_Wxs);
    cudaGetSymbolAddress((void**)&p_whs, g_Whs);
    cudaGetSymbolAddress((void**)&p_was, g_Was);
    cudaGetSymbolAddress((void**)&p_hsA, g_hsA);
    cudaGetSymbolAddress((void**)&p_hsB, g_hsB);

    constexpr int SM_P1 = 2 * (128 + 128) * 128;  // 65536
    constexpr int SM_ST = 2 * (64 + 64) * 128;    // 32768
    cudaFuncSetAttribute((const void*)gemm_mma<128, 128, 2, 4, 1>,
                         cudaFuncAttributeMaxDynamicSharedMemorySize, SM_P1);
    cudaFuncSetAttribute((const void*)gemm_mma<128, 128, 2, 4, 0>,
                         cudaFuncAttributeMaxDynamicSharedMemorySize, SM_P1);
    cudaFuncSetAttribute((const void*)gemm_mma<64, 64, 2, 2, 2>,
                         cudaFuncAttributeMaxDynamicSharedMemorySize, SM_ST);

    // prep
    x_split_kernel<<<(NB * TT * HH / 4) / 256, 256>>>(x);
    at_prep_kernel<<<(NB * HH) / 256, 256>>>(A);
    {
        dim3 g(GG / 32, HH / 32), blk(32, 8);
        wsplit_kernel<<<g, blk>>>(Wx, p_wxs);
        wsplit_kernel<<<g, blk>>>(Wh, p_whs);
        wsplit_kernel<<<g, blk>>>(Wattn, p_was);
    }
    bias_perm_kernel<<<GG / 256, 256>>>(b);

    // phase 1: XW = x' @ Wx'^T + b ; P = AT' @ Wa'^T
    {
        dim3 g(GG / 128, (NB * TT) / 128);
        gemm_mma<128, 128, 2, 4, 1><<<g, 256, SM_P1>>>(p_xs, p_wxs, p_xw, p_bp, nullptr, nullptr, 0);
    }
    {
        dim3 g(GG / 128, (NB * LL) / 128);
        gemm_mma<128, 128, 2, 4, 0><<<g, 256, SM_P1>>>(p_ats, p_was, p_p, nullptr, nullptr, nullptr, 0);
    }

    // phase 2: sequential scan, 2 launches per step
    for (int t = 0; t < TT; t++) {
        sc_combine_kernel<<<NB, 512>>>(t);
        __nv_bfloat16* hc = (t & 1) ? p_hsB : p_hsA;
        __nv_bfloat16* hn = (t & 1) ? p_hsA : p_hsB;
        dim3 g(GG / 64, NB / 64);
        gemm_mma<64, 64, 2, 2, 2><<<g, 128, SM_ST>>>(hc, p_whs, nullptr, p_z, hn, out, t);
    }
}

// round 14
// speedup vs baseline: 1.6085x; 1.2818x over previous
#include <cuda_runtime.h>
#include <cuda_bf16.h>
#include <cuda_fp16.h>
#include <math.h>
#include <stdint.h>

#define NB 256
#define TT 64
#define HH 1024
#define GG 4096
#define LL 16
#define KP 2048   // fp16 2-term split folded into K

__device__ __forceinline__ uint32_t smem_u32(const void* p) {
    uint32_t a;
    asm("{ .reg .u64 t; cvta.to.shared.u64 t, %1; cvt.u32.u64 %0, t; }" : "=r"(a) : "l"(p));
    return a;
}
#define CP16(dst, src) asm volatile("cp.async.cg.shared.global [%0], [%1], 16;" :: "r"(dst), "l"(src) : "memory")
#define CP_COMMIT() asm volatile("cp.async.commit_group;" ::: "memory")
#define CP_WAIT1() asm volatile("cp.async.wait_group 1;" ::: "memory")
#define LDSM4(r0, r1, r2, r3, addr) \
    asm volatile("ldmatrix.sync.aligned.m8n8.x4.shared.b16 {%0,%1,%2,%3}, [%4];" \
        : "=r"(r0), "=r"(r1), "=r"(r2), "=r"(r3) : "r"(addr))
#define MMA16816(d, a, b) \
    asm volatile("mma.sync.aligned.m16n8k16.row.col.f32.f16.f16.f32 " \
        "{%0,%1,%2,%3}, {%4,%5,%6,%7}, {%8,%9}, {%0,%1,%2,%3};" \
        : "+f"((d)[0]), "+f"((d)[1]), "+f"((d)[2]), "+f"((d)[3]) \
        : "r"((a)[0]), "r"((a)[1]), "r"((a)[2]), "r"((a)[3]), "r"((b)[0]), "r"((b)[1]))

// ------------------------------------------------ scratch
__device__ float g_XW[(size_t)NB * TT * GG];      // permuted cols, fp32
__device__ float g_P[(size_t)NB * LL * GG];       // permuted cols, fp32
__device__ float g_AT[(size_t)NB * LL * HH];      // fp32 for scores
__device__ float g_attnZ[(size_t)NB * GG];        // permuted cols
__device__ float g_h[NB * HH];
__device__ float g_c[NB * HH];
__device__ float g_bperm[GG];
__device__ __half g_xs[(size_t)NB * TT * KP];     // [xhi|xlo]
__device__ __half g_ATs[(size_t)NB * LL * KP];    // [hi|lo]
__device__ __half g_Wxs[(size_t)GG * KP];         // [Whi|Whi] (B side)
__device__ __half g_Whs[(size_t)GG * KP];
__device__ __half g_Was[(size_t)GG * KP];
__device__ __half g_hsA[(size_t)NB * KP];         // h ping [hi|lo]
__device__ __half g_hsB[(size_t)NB * KP];         // h pong

// ------------------------------------------------ prep kernels
__global__ void x_split_kernel(const float* __restrict__ x) {
    size_t gid = (size_t)blockIdx.x * 256 + threadIdx.x;  // float4 id
    size_t r = gid >> 8;
    int kq = (int)(gid & 255);
    float4 v = ((const float4*)x)[gid];
    __half2 h0 = __floats2half2_rn(v.x, v.y);
    __half2 h1 = __floats2half2_rn(v.z, v.w);
    float2 f0 = __half22float2(h0), f1 = __half22float2(h1);
    __half2 l0 = __floats2half2_rn(v.x - f0.x, v.y - f0.y);
    __half2 l1 = __floats2half2_rn(v.z - f1.x, v.w - f1.y);
    __half2* base = (__half2*)(g_xs + r * KP);
    base[kq * 2] = h0;        base[kq * 2 + 1] = h1;
    base[512 + kq * 2] = l0;  base[512 + kq * 2 + 1] = l1;
}

__global__ void at_prep_kernel(const float* __restrict__ A) {
    int idx = blockIdx.x * 256 + threadIdx.x;  // n*1024 + h
    int n = idx >> 10, h = idx & 1023;
    const float4* a4 = (const float4*)(A + (size_t)idx * 16);
    float s = 0.f;
#pragma unroll
    for (int q = 0; q < 4; q++) {
        float4 v = a4[q];
        float vv[4] = {v.x, v.y, v.z, v.w};
#pragma unroll
        for (int e = 0; e < 4; e++) {
            int l = q * 4 + e;
            float val = vv[e];
            g_AT[((size_t)n * LL + l) * HH + h] = val;
            __half hi = __float2half_rn(val);
            __half lo = __float2half_rn(val - __half2float(hi));
            size_t o = ((size_t)n * LL + l) * KP + h;
            g_ATs[o] = hi; g_ATs[o + 1024] = lo;
            s += val;
        }
    }
    float h0 = s * (1.0f / 16.0f);
    g_h[idx] = h0;
    g_c[idx] = h0;
    __half hh = __float2half_rn(h0);
    __half hl = __float2half_rn(h0 - __half2float(hh));
    size_t o = (size_t)n * KP + h;
    g_hsA[o] = hh; g_hsA[o + 1024] = hl;
}

// transpose + fp16 + permute: col c = g*1024+u -> rp = ((u>>3)<<5)|(g<<3)|(u&7)
// B side holds [Whi | Whi] (duplicated; A-side split carries the precision)
__global__ void wsplit_kernel(const float* __restrict__ W, __half* __restrict__ Ws) {
    __shared__ float tile[32][33];
    int c0 = blockIdx.x * 32, k0 = blockIdx.y * 32;
    int tx = threadIdx.x;
    for (int i = threadIdx.y; i < 32; i += 8)
        tile[i][tx] = W[(size_t)(k0 + i) * GG + c0 + tx];
    __syncthreads();
    for (int i = threadIdx.y; i < 32; i += 8) {
        int c = c0 + i;
        int u = c & 1023, g = c >> 10;
        int rp = ((u >> 3) << 5) | (g << 3) | (u & 7);
        __half hi = __float2half_rn(tile[tx][i]);
        size_t o = (size_t)rp * KP + k0 + tx;
        Ws[o] = hi; Ws[o + 1024] = hi;
    }
}

__global__ void bias_perm_kernel(const float* __restrict__ b) {
    int idx = blockIdx.x * 256 + threadIdx.x;   // permuted col
    int g = (idx >> 3) & 3;
    int u = (idx & 7) | ((idx >> 5) << 3);
    g_bperm[idx] = b[g * 1024 + u];
}

// ------------------------------------------------ mma.sync fp16 GEMM, K'=2048
// EPI: 0 plain, 1 +bias, 2 fused LSTM gates (BM=64, BN=64, 128 thr)
template <int BM, int BN, int WARPS_M, int WARPS_N, int EPI>
__global__ void __launch_bounds__(WARPS_M * WARPS_N * 32)
gemm_mma(const __half* __restrict__ Ag, const __half* __restrict__ Bg,
         float* __restrict__ Cout, const float* __restrict__ addv,
         __half* __restrict__ hnext, float* __restrict__ out, int t)
{
    constexpr int NTH = WARPS_M * WARPS_N * 32;
    constexpr int WM = BM / WARPS_M, WN = BN / WARPS_N;
    constexpr int MT = WM / 16, NT2 = WN / 8;
    constexpr int KC = KP / 64;
    constexpr int ABUF = BM * 128, BBUF = BN * 128;

    extern __shared__ char smem[];
    const uint32_t sA = smem_u32(smem);
    const uint32_t sB = sA + 2 * ABUF;
    const int tid = threadIdx.x, lane = tid & 31, warp = tid >> 5;
    const int wm0 = (warp / WARPS_N) * WM, wn0 = (warp % WARPS_N) * WN;
    const int m0 = blockIdx.y * BM, n0 = blockIdx.x * BN;
    const __half* Abase = Ag + (size_t)m0 * KP;
    const __half* Bbase = Bg + (size_t)n0 * KP;

    float acc[MT][NT2][4];
#pragma unroll
    for (int i = 0; i < MT; i++)
#pragma unroll
        for (int j = 0; j < NT2; j++)
#pragma unroll
            for (int e = 0; e < 4; e++) acc[i][j][e] = 0.f;

#define ISSUE1(kc, buf) do { \
    const __half* As_ = Abase + (kc) * 64; \
    _Pragma("unroll") \
    for (int i = 0; i < BM * 8 / NTH; i++) { \
        int idx = tid + i * NTH, r = idx >> 3, q = idx & 7; \
        CP16(sA + (buf) * ABUF + r * 128 + (((q ^ (r & 7)) << 4)), As_ + (size_t)r * KP + q * 8); \
    } \
    const __half* Bs_ = Bbase + (kc) * 64; \
    _Pragma("unroll") \
    for (int i = 0; i < BN * 8 / NTH; i++) { \
        int idx = tid + i * NTH, r = idx >> 3, q = idx & 7; \
        CP16(sB + (buf) * BBUF + r * 128 + (((q ^ (r & 7)) << 4)), Bs_ + (size_t)r * KP + q * 8); \
    } \
} while (0)

    ISSUE1(0, 0); CP_COMMIT();
    ISSUE1(1, 1); CP_COMMIT();

    for (int kc = 0; kc < KC; kc++) {
        CP_WAIT1();
        __syncthreads();
        const int buf = kc & 1;
        const uint32_t a0b = sA + buf * ABUF, b0b = sB + buf * BBUF;
#pragma unroll
        for (int ks = 0; ks < 4; ks++) {
            uint32_t af[MT][4], bf[NT2][2];
#pragma unroll
            for (int mt = 0; mt < MT; mt++) {
                int r = wm0 + mt * 16 + (lane & 15);
                int q = ks * 2 + (lane >> 4);
                LDSM4(af[mt][0], af[mt][1], af[mt][2], af[mt][3],
                      a0b + r * 128 + (((q ^ (r & 7)) << 4)));
            }
#pragma unroll
            for (int p = 0; p < NT2 / 2; p++) {
                int n = wn0 + p * 16 + (lane & 7) + ((lane >> 4) << 3);
                int q = ks * 2 + ((lane >> 3) & 1);
                LDSM4(bf[2 * p][0], bf[2 * p][1], bf[2 * p + 1][0], bf[2 * p + 1][1],
                      b0b + n * 128 + (((q ^ (n & 7)) << 4)));
            }
#pragma unroll
            for (int mt = 0; mt < MT; mt++)
#pragma unroll
                for (int nt = 0; nt < NT2; nt++)
                    MMA16816(acc[mt][nt], af[mt], bf[nt]);
        }
        __syncthreads();
        if (kc + 2 < KC) ISSUE1(kc + 2, buf);
        CP_COMMIT();
    }
#undef ISSUE1

    const int l4 = lane >> 2, q2 = (lane & 3) * 2;
    if (EPI != 2) {
#pragma unroll
        for (int mt = 0; mt < MT; mt++) {
            int r0 = m0 + wm0 + mt * 16 + l4;
#pragma unroll
            for (int nt = 0; nt < NT2; nt++) {
                int col = n0 + wn0 + nt * 8 + q2;
                float bx = 0.f, by = 0.f;
                if (EPI == 1) { bx = addv[col]; by = addv[col + 1]; }
                *(float2*)(Cout + (size_t)r0 * GG + col) =
                    make_float2(acc[mt][nt][0] + bx, acc[mt][nt][1] + by);
                *(float2*)(Cout + (size_t)(r0 + 8) * GG + col) =
                    make_float2(acc[mt][nt][2] + bx, acc[mt][nt][3] + by);
            }
        }
    } else {
        const int U0 = (((n0 + wn0) >> 5) << 3) + q2;
        const int cb = n0 + wn0 + q2;
#pragma unroll
        for (int mt = 0; mt < MT; mt++) {
#pragma unroll
            for (int rs = 0; rs < 2; rs++) {
                int row = m0 + wm0 + mt * 16 + l4 + rs * 8;
                const float* zr = addv + (size_t)row * GG + cb;
#pragma unroll
                for (int us = 0; us < 2; us++) {
                    float ai = acc[mt][0][rs * 2 + us] + zr[us];
                    float afv = acc[mt][1][rs * 2 + us] + zr[8 + us];
                    float ao = acc[mt][2][rs * 2 + us] + zr[16 + us];
                    float ag = acc[mt][3][rs * 2 + us] + zr[24 + us];
                    int u = U0 + us;
                    float gi = 1.f / (1.f + expf(-ai));
                    float gf = 1.f / (1.f + expf(-afv));
                    float go = 1.f / (1.f + expf(-ao));
                    float gg = tanhf(ag);
                    size_t hx = (size_t)row * HH + u;
                    float cn = gf * g_c[hx] + gi * gg;
                    g_c[hx] = cn;
                    float hn = go * tanhf(cn);
                    g_h[hx] = hn;
                    __half hh = __float2half_rn(hn);
                    __half hl = __float2half_rn(hn - __half2float(hh));
                    size_t hb = (size_t)row * KP + u;
                    hnext[hb] = hh; hnext[hb + 1024] = hl;
                    out[((size_t)row * TT + t) * HH + u] = hn;
                }
            }
        }
    }
}

// ------------------------------------------------ fused scores+softmax+combine
// One CTA per sample n, 512 threads (16 warps).
__global__ __launch_bounds__(512) void sc_combine_kernel(int t) {
    __shared__ float sw[16];
    const int n = blockIdx.x;
    const int tid = threadIdx.x, warp = tid >> 5, lane = tid & 31;

    {
        const float* hp = g_h + (size_t)n * HH;
        const float* ap = g_AT + ((size_t)n * LL + warp) * HH;
        float acc = 0.f;
        for (int k = lane; k < HH; k += 32) acc += hp[k] * ap[k];
#pragma unroll
        for (int o = 16; o > 0; o >>= 1) acc += __shfl_xor_sync(0xffffffffu, acc, o);
        if (lane == 0) sw[warp] = acc * 0.03125f;
    }
    __syncthreads();
    if (warp == 0) {
        float s = (lane < 16) ? sw[lane] : -1e30f;
        float m = s;
#pragma unroll
        for (int o = 16; o > 0; o >>= 1) m = fmaxf(m, __shfl_xor_sync(0xffffffffu, m, o));
        float e = (lane < 16) ? expf(s - m) : 0.f;
        float tot = e;
#pragma unroll
        for (int o = 16; o > 0; o >>= 1) tot += __shfl_xor_sync(0xffffffffu, tot, o);
        if (lane < 16) sw[lane] = e / tot;
    }
    __syncthreads();

    float wl[16];
#pragma unroll
    for (int l = 0; l < 16; l++) wl[l] = sw[l];

    const float4* xw4 = (const float4*)(g_XW + ((size_t)n * TT + t) * GG);
    const float4* p4 = (const float4*)(g_P + (size_t)n * LL * GG);
    float4* oz4 = (float4*)(g_attnZ + (size_t)n * GG);
#pragma unroll
    for (int it = 0; it < 2; it++) {
        int c = tid + it * 512;            // float4 idx 0..1023
        float4 a = xw4[c];
#pragma unroll
        for (int l = 0; l < 16; l++) {
            float4 pv = p4[(size_t)l * (GG / 4) + c];
            float w = wl[l];
            a.x += w * pv.x; a.y += w * pv.y; a.z += w * pv.z; a.w += w * pv.w;
        }
        oz4[c] = a;
    }
}

// ------------------------------------------------ launch
extern "C" void kernel_launch(void* const* d_in, const int* in_sizes, int n_in,
                              void* d_out, int out_size) {
    const float* x = (const float*)d_in[0];
    const float* A = (const float*)d_in[1];
    const float* Wx = (const float*)d_in[2];
    const float* Wh = (const float*)d_in[3];
    const float* Wattn = (const float*)d_in[4];
    const float* b = (const float*)d_in[5];
    float* out = (float*)d_out;

    float *p_xw, *p_p, *p_bp, *p_z;
    __half *p_xs, *p_ats, *p_wxs, *p_whs, *p_was, *p_hsA, *p_hsB;
    cudaGetSymbolAddress((void**)&p_xw, g_XW);
    cudaGetSymbolAddress((void**)&p_p, g_P);
    cudaGetSymbolAddress((void**)&p_bp, g_bperm);
    cudaGetSymbolAddress((void**)&p_z, g_attnZ);
    cudaGetSymbolAddress((void**)&p_xs, g_xs);
    cudaGetSymbolAddress((void**)&p_ats, g_ATs);
    cudaGetSymbolAddress((void**)&p_wxs, g_Wxs);
    cudaGetSymbolAddress((void**)&p_whs, g_Whs);
    cudaGetSymbolAddress((void**)&p_was, g_Was);
    cudaGetSymbolAddress((void**)&p_hsA, g_hsA);
    cudaGetSymbolAddress((void**)&p_hsB, g_hsB);

    constexpr int SM_P1 = 2 * (128 + 128) * 128;  // 65536
    constexpr int SM_ST = 2 * (64 + 64) * 128;    // 32768
    cudaFuncSetAttribute((const void*)gemm_mma<128, 128, 2, 4, 1>,
                         cudaFuncAttributeMaxDynamicSharedMemorySize, SM_P1);
    cudaFuncSetAttribute((const void*)gemm_mma<128, 128, 2, 4, 0>,
                         cudaFuncAttributeMaxDynamicSharedMemorySize, SM_P1);
    cudaFuncSetAttribute((const void*)gemm_mma<64, 64, 2, 2, 2>,
                         cudaFuncAttributeMaxDynamicSharedMemorySize, SM_ST);

    // prep
    x_split_kernel<<<(NB * TT * HH / 4) / 256, 256>>>(x);
    at_prep_kernel<<<(NB * HH) / 256, 256>>>(A);
    {
        dim3 g(GG / 32, HH / 32), blk(32, 8);
        wsplit_kernel<<<g, blk>>>(Wx, p_wxs);
        wsplit_kernel<<<g, blk>>>(Wh, p_whs);
        wsplit_kernel<<<g, blk>>>(Wattn, p_was);
    }
    bias_perm_kernel<<<GG / 256, 256>>>(b);

    // phase 1: XW = x' @ Wx'^T + b ; P = AT' @ Wa'^T
    {
        dim3 g(GG / 128, (NB * TT) / 128);
        gemm_mma<128, 128, 2, 4, 1><<<g, 256, SM_P1>>>(p_xs, p_wxs, p_xw, p_bp, nullptr, nullptr, 0);
    }
    {
        dim3 g(GG / 128, (NB * LL) / 128);
        gemm_mma<128, 128, 2, 4, 0><<<g, 256, SM_P1>>>(p_ats, p_was, p_p, nullptr, nullptr, nullptr, 0);
    }

    // phase 2: sequential scan, 2 launches per step
    for (int t = 0; t < TT; t++) {
        sc_combine_kernel<<<NB, 512>>>(t);
        __half* hc = (t & 1) ? p_hsB : p_hsA;
        __half* hn = (t & 1) ? p_hsA : p_hsB;
        dim3 g(GG / 64, NB / 64);
        gemm_mma<64, 64, 2, 2, 2><<<g, 128, SM_ST>>>(hc, p_whs, nullptr, p_z, hn, out, t);
    }
}

// round 15
// speedup vs baseline: 1.9490x; 1.2117x over previous
#include <cuda_runtime.h>
#include <cuda_bf16.h>
#include <cuda_fp16.h>
#include <math.h>
#include <stdint.h>

#define NB 256
#define TT 64
#define HH 1024
#define GG 4096
#define LL 16
#define KP 2048   // fp16 2-term split folded into K

__device__ __forceinline__ uint32_t smem_u32(const void* p) {
    uint32_t a;
    asm("{ .reg .u64 t; cvta.to.shared.u64 t, %1; cvt.u32.u64 %0, t; }" : "=r"(a) : "l"(p));
    return a;
}
#define CP16(dst, src) asm volatile("cp.async.cg.shared.global [%0], [%1], 16;" :: "r"(dst), "l"(src) : "memory")
#define CP_COMMIT() asm volatile("cp.async.commit_group;" ::: "memory")
#define CP_WAIT1() asm volatile("cp.async.wait_group 1;" ::: "memory")
#define LDSM4(r0, r1, r2, r3, addr) \
    asm volatile("ldmatrix.sync.aligned.m8n8.x4.shared.b16 {%0,%1,%2,%3}, [%4];" \
        : "=r"(r0), "=r"(r1), "=r"(r2), "=r"(r3) : "r"(addr))
#define MMA16816(d, a, b) \
    asm volatile("mma.sync.aligned.m16n8k16.row.col.f32.f16.f16.f32 " \
        "{%0,%1,%2,%3}, {%4,%5,%6,%7}, {%8,%9}, {%0,%1,%2,%3};" \
        : "+f"((d)[0]), "+f"((d)[1]), "+f"((d)[2]), "+f"((d)[3]) \
        : "r"((a)[0]), "r"((a)[1]), "r"((a)[2]), "r"((a)[3]), "r"((b)[0]), "r"((b)[1]))

// ------------------------------------------------ scratch
__device__ float g_XW[(size_t)NB * TT * GG];      // permuted cols, fp32
__device__ __half g_Ph[(size_t)NB * LL * GG];     // permuted cols, fp16
__device__ float g_AT[(size_t)NB * LL * HH];      // fp32 for scores
__device__ float g_attnZ[(size_t)NB * GG];        // permuted cols
__device__ float g_h[NB * HH];
__device__ float g_c[NB * HH];
__device__ float g_bperm[GG];
__device__ __half g_xs[(size_t)NB * TT * KP];     // [xhi|xlo]
__device__ __half g_ATs[(size_t)NB * LL * KP];    // [hi|lo]
__device__ __half g_Wxs[(size_t)GG * KP];         // [Whi|Whi] (B side)
__device__ __half g_Whs[(size_t)GG * KP];
__device__ __half g_Was[(size_t)GG * KP];
__device__ __half g_hsA[(size_t)NB * KP];         // h ping [hi|lo]
__device__ __half g_hsB[(size_t)NB * KP];         // h pong

// ------------------------------------------------ prep kernels
__global__ void x_split_kernel(const float* __restrict__ x) {
    size_t gid = (size_t)blockIdx.x * 256 + threadIdx.x;  // float4 id
    size_t r = gid >> 8;
    int kq = (int)(gid & 255);
    float4 v = ((const float4*)x)[gid];
    __half2 h0 = __floats2half2_rn(v.x, v.y);
    __half2 h1 = __floats2half2_rn(v.z, v.w);
    float2 f0 = __half22float2(h0), f1 = __half22float2(h1);
    __half2 l0 = __floats2half2_rn(v.x - f0.x, v.y - f0.y);
    __half2 l1 = __floats2half2_rn(v.z - f1.x, v.w - f1.y);
    __half2* base = (__half2*)(g_xs + r * KP);
    base[kq * 2] = h0;        base[kq * 2 + 1] = h1;
    base[512 + kq * 2] = l0;  base[512 + kq * 2 + 1] = l1;
}

__global__ void at_prep_kernel(const float* __restrict__ A) {
    int idx = blockIdx.x * 256 + threadIdx.x;  // n*1024 + h
    int n = idx >> 10, h = idx & 1023;
    const float4* a4 = (const float4*)(A + (size_t)idx * 16);
    float s = 0.f;
#pragma unroll
    for (int q = 0; q < 4; q++) {
        float4 v = a4[q];
        float vv[4] = {v.x, v.y, v.z, v.w};
#pragma unroll
        for (int e = 0; e < 4; e++) {
            int l = q * 4 + e;
            float val = vv[e];
            g_AT[((size_t)n * LL + l) * HH + h] = val;
            __half hi = __float2half_rn(val);
            __half lo = __float2half_rn(val - __half2float(hi));
            size_t o = ((size_t)n * LL + l) * KP + h;
            g_ATs[o] = hi; g_ATs[o + 1024] = lo;
            s += val;
        }
    }
    float h0 = s * (1.0f / 16.0f);
    g_h[idx] = h0;
    g_c[idx] = h0;
    __half hh = __float2half_rn(h0);
    __half hl = __float2half_rn(h0 - __half2float(hh));
    size_t o = (size_t)n * KP + h;
    g_hsA[o] = hh; g_hsA[o + 1024] = hl;
}

// transpose + fp16 + permute: col c = g*1024+u -> rp = ((u>>3)<<5)|(g<<3)|(u&7)
__global__ void wsplit_kernel(const float* __restrict__ W, __half* __restrict__ Ws) {
    __shared__ float tile[32][33];
    int c0 = blockIdx.x * 32, k0 = blockIdx.y * 32;
    int tx = threadIdx.x;
    for (int i = threadIdx.y; i < 32; i += 8)
        tile[i][tx] = W[(size_t)(k0 + i) * GG + c0 + tx];
    __syncthreads();
    for (int i = threadIdx.y; i < 32; i += 8) {
        int c = c0 + i;
        int u = c & 1023, g = c >> 10;
        int rp = ((u >> 3) << 5) | (g << 3) | (u & 7);
        __half hi = __float2half_rn(tile[tx][i]);
        size_t o = (size_t)rp * KP + k0 + tx;
        Ws[o] = hi; Ws[o + 1024] = hi;
    }
}

__global__ void bias_perm_kernel(const float* __restrict__ b) {
    int idx = blockIdx.x * 256 + threadIdx.x;   // permuted col
    int g = (idx >> 3) & 3;
    int u = (idx & 7) | ((idx >> 5) << 3);
    g_bperm[idx] = b[g * 1024 + u];
}

// ------------------------------------------------ mma.sync fp16 GEMM, K'=2048
// EPI: 0 plain fp32, 1 +bias fp32, 2 fused LSTM gates, 3 fp16 store
template <int BM, int BN, int WARPS_M, int WARPS_N, int EPI>
__global__ void __launch_bounds__(WARPS_M * WARPS_N * 32)
gemm_mma(const __half* __restrict__ Ag, const __half* __restrict__ Bg,
         float* __restrict__ Cout, const float* __restrict__ addv,
         __half* __restrict__ hnext, float* __restrict__ out, int t)
{
    constexpr int NTH = WARPS_M * WARPS_N * 32;
    constexpr int WM = BM / WARPS_M, WN = BN / WARPS_N;
    constexpr int MT = WM / 16, NT2 = WN / 8;
    constexpr int KC = KP / 64;
    constexpr int ABUF = BM * 128, BBUF = BN * 128;

    extern __shared__ char smem[];
    const uint32_t sA = smem_u32(smem);
    const uint32_t sB = sA + 2 * ABUF;
    const int tid = threadIdx.x, lane = tid & 31, warp = tid >> 5;
    const int wm0 = (warp / WARPS_N) * WM, wn0 = (warp % WARPS_N) * WN;
    const int m0 = blockIdx.y * BM, n0 = blockIdx.x * BN;
    const __half* Abase = Ag + (size_t)m0 * KP;
    const __half* Bbase = Bg + (size_t)n0 * KP;

    float acc[MT][NT2][4];
#pragma unroll
    for (int i = 0; i < MT; i++)
#pragma unroll
        for (int j = 0; j < NT2; j++)
#pragma unroll
            for (int e = 0; e < 4; e++) acc[i][j][e] = 0.f;

#define ISSUE1(kc, buf) do { \
    const __half* As_ = Abase + (kc) * 64; \
    _Pragma("unroll") \
    for (int i = 0; i < BM * 8 / NTH; i++) { \
        int idx = tid + i * NTH, r = idx >> 3, q = idx & 7; \
        CP16(sA + (buf) * ABUF + r * 128 + (((q ^ (r & 7)) << 4)), As_ + (size_t)r * KP + q * 8); \
    } \
    const __half* Bs_ = Bbase + (kc) * 64; \
    _Pragma("unroll") \
    for (int i = 0; i < BN * 8 / NTH; i++) { \
        int idx = tid + i * NTH, r = idx >> 3, q = idx & 7; \
        CP16(sB + (buf) * BBUF + r * 128 + (((q ^ (r & 7)) << 4)), Bs_ + (size_t)r * KP + q * 8); \
    } \
} while (0)

    ISSUE1(0, 0); CP_COMMIT();
    ISSUE1(1, 1); CP_COMMIT();

    for (int kc = 0; kc < KC; kc++) {
        CP_WAIT1();
        __syncthreads();
        const int buf = kc & 1;
        const uint32_t a0b = sA + buf * ABUF, b0b = sB + buf * BBUF;
#pragma unroll
        for (int ks = 0; ks < 4; ks++) {
            uint32_t af[MT][4], bf[NT2][2];
#pragma unroll
            for (int mt = 0; mt < MT; mt++) {
                int r = wm0 + mt * 16 + (lane & 15);
                int q = ks * 2 + (lane >> 4);
                LDSM4(af[mt][0], af[mt][1], af[mt][2], af[mt][3],
                      a0b + r * 128 + (((q ^ (r & 7)) << 4)));
            }
#pragma unroll
            for (int p = 0; p < NT2 / 2; p++) {
                int n = wn0 + p * 16 + (lane & 7) + ((lane >> 4) << 3);
                int q = ks * 2 + ((lane >> 3) & 1);
                LDSM4(bf[2 * p][0], bf[2 * p][1], bf[2 * p + 1][0], bf[2 * p + 1][1],
                      b0b + n * 128 + (((q ^ (n & 7)) << 4)));
            }
#pragma unroll
            for (int mt = 0; mt < MT; mt++)
#pragma unroll
                for (int nt = 0; nt < NT2; nt++)
                    MMA16816(acc[mt][nt], af[mt], bf[nt]);
        }
        __syncthreads();
        if (kc + 2 < KC) ISSUE1(kc + 2, buf);
        CP_COMMIT();
    }
#undef ISSUE1

    const int l4 = lane >> 2, q2 = (lane & 3) * 2;
    if (EPI == 0 || EPI == 1) {
#pragma unroll
        for (int mt = 0; mt < MT; mt++) {
            int r0 = m0 + wm0 + mt * 16 + l4;
#pragma unroll
            for (int nt = 0; nt < NT2; nt++) {
                int col = n0 + wn0 + nt * 8 + q2;
                float bx = 0.f, by = 0.f;
                if (EPI == 1) { bx = addv[col]; by = addv[col + 1]; }
                *(float2*)(Cout + (size_t)r0 * GG + col) =
                    make_float2(acc[mt][nt][0] + bx, acc[mt][nt][1] + by);
                *(float2*)(Cout + (size_t)(r0 + 8) * GG + col) =
                    make_float2(acc[mt][nt][2] + bx, acc[mt][nt][3] + by);
            }
        }
    } else if (EPI == 3) {
        __half* Ch = (__half*)Cout;
#pragma unroll
        for (int mt = 0; mt < MT; mt++) {
            int r0 = m0 + wm0 + mt * 16 + l4;
#pragma unroll
            for (int nt = 0; nt < NT2; nt++) {
                int col = n0 + wn0 + nt * 8 + q2;
                *(__half2*)(Ch + (size_t)r0 * GG + col) =
                    __floats2half2_rn(acc[mt][nt][0], acc[mt][nt][1]);
                *(__half2*)(Ch + (size_t)(r0 + 8) * GG + col) =
                    __floats2half2_rn(acc[mt][nt][2], acc[mt][nt][3]);
            }
        }
    } else {
        const int U0 = (((n0 + wn0) >> 5) << 3) + q2;
        const int cb = n0 + wn0 + q2;
#pragma unroll
        for (int mt = 0; mt < MT; mt++) {
#pragma unroll
            for (int rs = 0; rs < 2; rs++) {
                int row = m0 + wm0 + mt * 16 + l4 + rs * 8;
                const float* zr = addv + (size_t)row * GG + cb;
#pragma unroll
                for (int us = 0; us < 2; us++) {
                    float ai = acc[mt][0][rs * 2 + us] + zr[us];
                    float afv = acc[mt][1][rs * 2 + us] + zr[8 + us];
                    float ao = acc[mt][2][rs * 2 + us] + zr[16 + us];
                    float ag = acc[mt][3][rs * 2 + us] + zr[24 + us];
                    int u = U0 + us;
                    float gi = 1.f / (1.f + expf(-ai));
                    float gf = 1.f / (1.f + expf(-afv));
                    float go = 1.f / (1.f + expf(-ao));
                    float gg = tanhf(ag);
                    size_t hx = (size_t)row * HH + u;
                    float cn = gf * g_c[hx] + gi * gg;
                    g_c[hx] = cn;
                    float hn = go * tanhf(cn);
                    g_h[hx] = hn;
                    __half hh = __float2half_rn(hn);
                    __half hl = __float2half_rn(hn - __half2float(hh));
                    size_t hb = (size_t)row * KP + u;
                    hnext[hb] = hh; hnext[hb + 1024] = hl;
                    out[((size_t)row * TT + t) * HH + u] = hn;
                }
            }
        }
    }
}

// ------------------------------------------------ fused scores+softmax+combine
// One CTA per sample n, 512 threads; each thread covers 8 columns.
__global__ __launch_bounds__(512) void sc_combine_kernel(int t) {
    __shared__ float sw[16];
    const int n = blockIdx.x;
    const int tid = threadIdx.x, warp = tid >> 5, lane = tid & 31;

    {
        const float* hp = g_h + (size_t)n * HH;
        const float* ap = g_AT + ((size_t)n * LL + warp) * HH;
        float acc = 0.f;
        for (int k = lane; k < HH; k += 32) acc += hp[k] * ap[k];
#pragma unroll
        for (int o = 16; o > 0; o >>= 1) acc += __shfl_xor_sync(0xffffffffu, acc, o);
        if (lane == 0) sw[warp] = acc * 0.03125f;
    }
    __syncthreads();
    if (warp == 0) {
        float s = (lane < 16) ? sw[lane] : -1e30f;
        float m = s;
#pragma unroll
        for (int o = 16; o > 0; o >>= 1) m = fmaxf(m, __shfl_xor_sync(0xffffffffu, m, o));
        float e = (lane < 16) ? expf(s - m) : 0.f;
        float tot = e;
#pragma unroll
        for (int o = 16; o > 0; o >>= 1) tot += __shfl_xor_sync(0xffffffffu, tot, o);
        if (lane < 16) sw[lane] = e / tot;
    }
    __syncthreads();

    float wl[16];
#pragma unroll
    for (int l = 0; l < 16; l++) wl[l] = sw[l];

    // 8 columns per thread: XW two float4, P one uint4 (8 halves) per l
    const int c8 = tid * 8;
    const float4* xw4 = (const float4*)(g_XW + ((size_t)n * TT + t) * GG + c8);
    float4 a0 = xw4[0], a1 = xw4[1];
    const __half* pb = g_Ph + (size_t)n * LL * GG + c8;
#pragma unroll
    for (int l = 0; l < 16; l++) {
        uint4 pv = *(const uint4*)(pb + (size_t)l * GG);
        float w = wl[l];
        float2 f0 = __half22float2(*(__half2*)&pv.x);
        float2 f1 = __half22float2(*(__half2*)&pv.y);
        float2 f2 = __half22float2(*(__half2*)&pv.z);
        float2 f3 = __half22float2(*(__half2*)&pv.w);
        a0.x += w * f0.x; a0.y += w * f0.y; a0.z += w * f1.x; a0.w += w * f1.y;
        a1.x += w * f2.x; a1.y += w * f2.y; a1.z += w * f3.x; a1.w += w * f3.y;
    }
    float4* oz4 = (float4*)(g_attnZ + (size_t)n * GG + c8);
    oz4[0] = a0; oz4[1] = a1;
}

// ------------------------------------------------ launch
extern "C" void kernel_launch(void* const* d_in, const int* in_sizes, int n_in,
                              void* d_out, int out_size) {
    const float* x = (const float*)d_in[0];
    const float* A = (const float*)d_in[1];
    const float* Wx = (const float*)d_in[2];
    const float* Wh = (const float*)d_in[3];
    const float* Wattn = (const float*)d_in[4];
    const float* b = (const float*)d_in[5];
    float* out = (float*)d_out;

    float *p_xw, *p_bp, *p_z;
    __half *p_ph, *p_xs, *p_ats, *p_wxs, *p_whs, *p_was, *p_hsA, *p_hsB;
    cudaGetSymbolAddress((void**)&p_xw, g_XW);
    cudaGetSymbolAddress((void**)&p_ph, g_Ph);
    cudaGetSymbolAddress((void**)&p_bp, g_bperm);
    cudaGetSymbolAddress((void**)&p_z, g_attnZ);
    cudaGetSymbolAddress((void**)&p_xs, g_xs);
    cudaGetSymbolAddress((void**)&p_ats, g_ATs);
    cudaGetSymbolAddress((void**)&p_wxs, g_Wxs);
    cudaGetSymbolAddress((void**)&p_whs, g_Whs);
    cudaGetSymbolAddress((void**)&p_was, g_Was);
    cudaGetSymbolAddress((void**)&p_hsA, g_hsA);
    cudaGetSymbolAddress((void**)&p_hsB, g_hsB);

    constexpr int SM_P1 = 2 * (128 + 128) * 128;  // 65536
    constexpr int SM_ST = 2 * (128 + 64) * 128;   // 49152
    cudaFuncSetAttribute((const void*)gemm_mma<128, 128, 2, 4, 1>,
                         cudaFuncAttributeMaxDynamicSharedMemorySize, SM_P1);
    cudaFuncSetAttribute((const void*)gemm_mma<128, 128, 2, 4, 3>,
                         cudaFuncAttributeMaxDynamicSharedMemorySize, SM_P1);
    cudaFuncSetAttribute((const void*)gemm_mma<128, 64, 4, 2, 2>,
                         cudaFuncAttributeMaxDynamicSharedMemorySize, SM_ST);

    // prep
    x_split_kernel<<<(NB * TT * HH / 4) / 256, 256>>>(x);
    at_prep_kernel<<<(NB * HH) / 256, 256>>>(A);
    {
        dim3 g(GG / 32, HH / 32), blk(32, 8);
        wsplit_kernel<<<g, blk>>>(Wx, p_wxs);
        wsplit_kernel<<<g, blk>>>(Wh, p_whs);
        wsplit_kernel<<<g, blk>>>(Wattn, p_was);
    }
    bias_perm_kernel<<<GG / 256, 256>>>(b);

    // phase 1: XW = x' @ Wx'^T + b ; P = AT' @ Wa'^T (fp16 store)
    {
        dim3 g(GG / 128, (NB * TT) / 128);
        gemm_mma<128, 128, 2, 4, 1><<<g, 256, SM_P1>>>(p_xs, p_wxs, p_xw, p_bp, nullptr, nullptr, 0);
    }
    {
        dim3 g(GG / 128, (NB * LL) / 128);
        gemm_mma<128, 128, 2, 4, 3><<<g, 256, SM_P1>>>(p_ats, p_was, (float*)p_ph, nullptr, nullptr, nullptr, 0);
    }

    // phase 2: sequential scan, 2 launches per step
    for (int t = 0; t < TT; t++) {
        sc_combine_kernel<<<NB, 512>>>(t);
        __half* hc = (t & 1) ? p_hsB : p_hsA;
        __half* hn = (t & 1) ? p_hsA : p_hsB;
        dim3 g(GG / 64, NB / 128);
        gemm_mma<128, 64, 4, 2, 2><<<g, 256, SM_ST>>>(hc, p_whs, nullptr, p_z, hn, out, t);
    }
}